// round 15
// baseline (speedup 1.0000x reference)
#include <cuda_runtime.h>
#include <cuda_bf16.h>
#include <cstdint>

#define D 128
#define NMAX 50000
#define TTYPES 4
#define AST 136                      // bf16 elems per smem row (ldmatrix pad)

// k_edge_mlp layout: Ah [0,34816) Al [34816,69632)
//                    S  [69632,137216)  (f32 [128][132])
//                    RAW[137216,204800) (f32 [128][132], padded stride)
#define P_HALF 34816
#define P_S    69632
#define P_RAW  137216
#define P_SMEM 204800

// k_final layout: Ah [0,34816) Al [34816,69632)
//                 Bbuf0 [69632,139264) Bbuf1 [139264,208896)
#define V_HALF 34816
#define V_B0   69632
#define V_BSZ  69632
#define V_SMEM 208896

// Scratch (device globals: allocation-free rule)
__device__ float g_A[(size_t)TTYPES * NMAX * D];   // per-type scatter of x[col]
__device__ float g_S[(size_t)NMAX * D];            // scatter of relu(ef@W1+b1)
__device__ int   g_cnt[TTYPES * NMAX];             // per (type,node) edge counts
// pre-split weights: [0..3]=W_types, [4]=W_e2, [5]=W_self, [6]=W1
__device__ __nv_bfloat16 g_Wh[7 * D * D];
__device__ __nv_bfloat16 g_Wl[7 * D * D];

// ---------------------------------------------------------------------------
__device__ __forceinline__ uint32_t smem_u32(const void* p) {
    return (uint32_t)__cvta_generic_to_shared(p);
}
__device__ __forceinline__ void split_bf(float a, __nv_bfloat16& h, __nv_bfloat16& l) {
    h = __float2bfloat16_rn(a);
    l = __float2bfloat16_rn(a - __bfloat162float(h));
}
__device__ __forceinline__ void store4_split(__nv_bfloat16* Hrow, __nv_bfloat16* Lrow,
                                             int c, float4 v) {
    __nv_bfloat16 h0, l0, h1, l1, h2, l2, h3, l3;
    split_bf(v.x, h0, l0); split_bf(v.y, h1, l1);
    split_bf(v.z, h2, l2); split_bf(v.w, h3, l3);
    *(__nv_bfloat162*)(Hrow + c)     = __halves2bfloat162(h0, h1);
    *(__nv_bfloat162*)(Hrow + c + 2) = __halves2bfloat162(h2, h3);
    *(__nv_bfloat162*)(Lrow + c)     = __halves2bfloat162(l0, l1);
    *(__nv_bfloat162*)(Lrow + c + 2) = __halves2bfloat162(l2, l3);
}

#define LDMX4(r0, r1, r2, r3, addr) \
    asm volatile("ldmatrix.sync.aligned.m8n8.x4.shared.b16 {%0,%1,%2,%3},[%4];" \
                 : "=r"(r0), "=r"(r1), "=r"(r2), "=r"(r3) : "r"(addr))
#define LDMX2T(r0, r1, addr) \
    asm volatile("ldmatrix.sync.aligned.m8n8.x2.trans.shared.b16 {%0,%1},[%2];" \
                 : "=r"(r0), "=r"(r1) : "r"(addr))
#define MMA_BF16(d, a0, a1, a2, a3, b0, b1) \
    asm volatile("mma.sync.aligned.m16n8k16.row.col.f32.bf16.bf16.f32 " \
                 "{%0,%1,%2,%3},{%4,%5,%6,%7},{%8,%9},{%0,%1,%2,%3};" \
                 : "+f"(d[0]), "+f"(d[1]), "+f"(d[2]), "+f"(d[3]) \
                 : "r"(a0), "r"(a1), "r"(a2), "r"(a3), "r"(b0), "r"(b1))
#define REDV4(ptr, v0, v1, v2, v3) \
    asm volatile("red.global.add.v4.f32 [%0], {%1,%2,%3,%4};" \
                 :: "l"(ptr), "f"(v0), "f"(v1), "f"(v2), "f"(v3) : "memory")
#define CP_ASYNC16(dst, src, sz) \
    asm volatile("cp.async.cg.shared.global [%0], [%1], 16, %2;" \
                 :: "r"(dst), "l"(src), "r"(sz) : "memory")
#define CP_COMMIT() asm volatile("cp.async.commit_group;" ::: "memory")
#define CP_WAIT0()  asm volatile("cp.async.wait_group 0;" ::: "memory")
#define CP_WAIT1()  asm volatile("cp.async.wait_group 1;" ::: "memory")

// ---------------------------------------------------------------------------
__global__ void k_split_w(const float* __restrict__ Wt, const float* __restrict__ We2,
                          const float* __restrict__ Wself, const float* __restrict__ W1) {
    int i = blockIdx.x * blockDim.x + threadIdx.x;
    int idx = i * 2;
    if (idx >= 7 * D * D) return;
    int m = idx / (D * D), r = idx % (D * D);
    const float* src = (m < 4) ? (Wt + (size_t)m * D * D + r)
                     : (m == 4 ? We2 + r : (m == 5 ? Wself + r : W1 + r));
    float2 v = *(const float2*)src;
    __nv_bfloat16 h0, l0, h1, l1;
    split_bf(v.x, h0, l0); split_bf(v.y, h1, l1);
    *(__nv_bfloat162*)(g_Wh + idx) = __halves2bfloat162(h0, h1);
    *(__nv_bfloat162*)(g_Wl + idx) = __halves2bfloat162(l0, l1);
}

// ---------------------------------------------------------------------------
__global__ void k_zero(int N) {
    size_t nA4 = (size_t)TTYPES * N * D / 4;
    size_t nS4 = (size_t)N * D / 4;
    size_t nC  = (size_t)TTYPES * N;
    size_t stride = (size_t)gridDim.x * blockDim.x;
    size_t i0 = (size_t)blockIdx.x * blockDim.x + threadIdx.x;
    float4 z = make_float4(0.f, 0.f, 0.f, 0.f);
    float4* A4 = (float4*)g_A;
    float4* S4 = (float4*)g_S;
    for (size_t i = i0; i < nA4; i += stride) A4[i] = z;
    for (size_t i = i0; i < nS4; i += stride) S4[i] = z;
    for (size_t i = i0; i < nC;  i += stride) g_cnt[i] = 0;
}

// ---------------------------------------------------------------------------
// One warp per edge: g_A[type][row] += x[col] (red.v4); counts.
__global__ void k_scatter(const float* __restrict__ x, const int* __restrict__ ei,
                          const int* __restrict__ et, int N, int E) {
    int w = (int)(((size_t)blockIdx.x * blockDim.x + threadIdx.x) >> 5);
    int lane = threadIdx.x & 31;
    if (w >= E) return;
    int row = __ldg(ei + w);
    int col = __ldg(ei + E + w);
    int t   = __ldg(et + w);
    float4 v = *(const float4*)(x + (size_t)col * D + lane * 4);
    float* p = g_A + ((size_t)t * N + row) * D + lane * 4;
    REDV4(p, v.x, v.y, v.z, v.w);
    if (lane == 0) atomicAdd(&g_cnt[t * N + row], 1);
}

// ---------------------------------------------------------------------------
// Stage one tile's raw ef fp32 -> RAW [128][132] (zfill OOB rows).
__device__ __forceinline__ void stage_tile(char* smem, const float* __restrict__ ef,
                                           int tile, int ntiles, int E, int tid) {
    if (tile >= ntiles) return;
    size_t e0 = (size_t)tile * 128;
    uint32_t raw = smem_u32(smem + P_RAW);
    #pragma unroll
    for (int i = 0; i < 16; i++) {
        int idx = tid + i * 256;
        int row = idx >> 5, c4 = idx & 31;
        size_t e = e0 + row;
        uint32_t sz = (e < (size_t)E) ? 16u : 0u;
        CP_ASYNC16(raw + (uint32_t)(row * 528 + c4 * 16), ef + e * D + c4 * 4, sz);
    }
    CP_COMMIT();
}

// Convert one column-grouped iteration: RAW fp32 -> split-bf16 A, cols [8t,8t+8).
__device__ __forceinline__ void conv_iter(char* smem, int t, int tid) {
    int row = tid & 127;
    int c4f = t * 2 + (tid >> 7);
    const float* RAW = (const float*)(smem + P_RAW);
    float4 v = *(const float4*)(RAW + row * 132 + c4f * 4);
    store4_split((__nv_bfloat16*)smem + row * AST,
                 (__nv_bfloat16*)(smem + P_HALF) + row * AST, c4f * 4, v);
}

// Persistent edge MLP: reg-resident W1 fragments, in-place A pipeline —
// the next tile's convert trails this tile's MMA column-block by column-block.
__global__ void __launch_bounds__(256, 1)
k_edge_mlp(const float* __restrict__ ef, const int* __restrict__ ei,
           const float* __restrict__ b1, int E, int ntiles) {
    extern __shared__ char smem[];
    uint32_t sb = smem_u32(smem);
    float* S = (float*)(smem + P_S);
    int tid = threadIdx.x, wid = tid >> 5, lane = tid & 31;
    int rg = wid & 1, cg = wid >> 1;

    stage_tile(smem, ef, blockIdx.x, ntiles, E, tid);   // tile0 -> RAW

    // Stage W1 into A region, extract B fragments into registers.
    {
        __nv_bfloat16* Bh = (__nv_bfloat16*)smem;
        __nv_bfloat16* Bl = (__nv_bfloat16*)(smem + P_HALF);
        const uint4* srcH = (const uint4*)(g_Wh + (size_t)6 * D * D);
        const uint4* srcL = (const uint4*)(g_Wl + (size_t)6 * D * D);
        for (int f = tid; f < 2048; f += 256) {
            int k = f >> 4, c8 = (f & 15) * 8;
            *(uint4*)(Bh + k * AST + c8) = srcH[f];
            *(uint4*)(Bl + k * AST + c8) = srcL[f];
        }
    }
    __syncthreads();
    uint32_t bh_r[8][4][2], bl_r[8][4][2];
    #pragma unroll
    for (int ks = 0; ks < 8; ks++) {
        #pragma unroll
        for (int nt = 0; nt < 4; nt++) {
            uint32_t ba = sb + (uint32_t)(((ks * 16 + (lane & 15)) * AST
                                           + cg * 32 + nt * 8) * 2);
            LDMX2T(bh_r[ks][nt][0], bh_r[ks][nt][1], ba);
            LDMX2T(bl_r[ks][nt][0], bl_r[ks][nt][1], ba + P_HALF);
        }
    }
    // per-warp bias for owned columns
    float2 bb2[4];
    #pragma unroll
    for (int nt = 0; nt < 4; nt++)
        bb2[nt] = *(const float2*)(b1 + cg * 32 + nt * 8 + (lane & 3) * 2);

    CP_WAIT0();                 // own RAW(tile0) copies complete
    __syncthreads();            // publish cross-thread; B-frag reads also done
    #pragma unroll
    for (int t = 0; t < 16; t++) conv_iter(smem, t, tid);   // A = tile0
    __syncthreads();            // A ready; RAW reads done
    stage_tile(smem, ef, blockIdx.x + (int)gridDim.x, ntiles, E, tid);

    for (int tile = blockIdx.x; tile < ntiles; tile += gridDim.x) {
        size_t e0 = (size_t)tile * 128;

        float acc[4][4][4] = {};
        #pragma unroll
        for (int ksp = 0; ksp < 4; ksp++) {
            #pragma unroll
            for (int kh = 0; kh < 2; kh++) {
                int ks = ksp * 2 + kh;
                #pragma unroll
                for (int rt = 0; rt < 4; rt++) {
                    uint32_t ao = sb + (uint32_t)(((rg * 64 + rt * 16 + (lane & 15)) * AST
                                                   + (lane >> 4) * 8 + ks * 16) * 2);
                    uint32_t ah0, ah1, ah2, ah3, al0, al1, al2, al3;
                    LDMX4(ah0, ah1, ah2, ah3, ao);
                    LDMX4(al0, al1, al2, al3, ao + P_HALF);
                    #pragma unroll
                    for (int nt = 0; nt < 4; nt++) {
                        MMA_BF16(acc[rt][nt], al0, al1, al2, al3,
                                 bh_r[ks][nt][0], bh_r[ks][nt][1]);
                        MMA_BF16(acc[rt][nt], ah0, ah1, ah2, ah3,
                                 bl_r[ks][nt][0], bl_r[ks][nt][1]);
                        MMA_BF16(acc[rt][nt], ah0, ah1, ah2, ah3,
                                 bh_r[ks][nt][0], bh_r[ks][nt][1]);
                    }
                }
            }
            // Next tile's RAW must be complete before the first conv batch.
            // Waiting here (after the ks=2ksp,2ksp+1 MMAs issued) hides the
            // fetch under the scatter + first MMA chunk; the barrier below
            // publishes the copies block-wide.
            if (ksp == 0) CP_WAIT0();
            __syncthreads();    // cols [32ksp, 32ksp+32) dead for all warps
            // convert next tile into those columns (in place)
            #pragma unroll
            for (int t = ksp * 4; t < ksp * 4 + 4; t++) conv_iter(smem, t, tid);
        }

        // acc + bias, ReLU -> S (full rows for contiguous scatter)
        {
            int cp = (lane & 3) * 2;
            #pragma unroll
            for (int rt = 0; rt < 4; rt++) {
                int r0 = rg * 64 + rt * 16 + (lane >> 2);
                #pragma unroll
                for (int nt = 0; nt < 4; nt++) {
                    int c = cg * 32 + nt * 8 + cp;
                    S[r0 * 132 + c]           = fmaxf(acc[rt][nt][0] + bb2[nt].x, 0.f);
                    S[r0 * 132 + c + 1]       = fmaxf(acc[rt][nt][1] + bb2[nt].y, 0.f);
                    S[(r0 + 8) * 132 + c]     = fmaxf(acc[rt][nt][2] + bb2[nt].x, 0.f);
                    S[(r0 + 8) * 132 + c + 1] = fmaxf(acc[rt][nt][3] + bb2[nt].y, 0.f);
                }
            }
        }
        __syncthreads();        // S ready; all converts + RAW reads done

        // scatter: warp w handles edges [w*16, w*16+16), coalesced red.v4
        #pragma unroll
        for (int it = 0; it < 16; it++) {
            int el = wid * 16 + it;
            size_t e = e0 + el;
            if (e < (size_t)E) {
                int dst = __ldg(ei + e);
                const float* Sr = S + el * 132 + lane * 4;
                float4 sv = *(const float4*)Sr;
                REDV4(g_S + (size_t)dst * D + lane * 4, sv.x, sv.y, sv.z, sv.w);
            }
        }
        stage_tile(smem, ef, tile + 2 * (int)gridDim.x, ntiles, E, tid);
        __syncthreads();        // S reads done before next overwrite
    }
}

// ---------------------------------------------------------------------------
// k_final: 128-node tiles, 512 threads, cp.async double-buffered B,
// register-prefetched A. 6 K-segments, then biases + LayerNorm + ReLU.
__device__ __forceinline__ const float* seg_src(int seg, const float* x, int N) {
    return (seg < 4) ? (g_A + (size_t)seg * N * D) : (seg == 4 ? g_S : x);
}
__device__ __forceinline__ void prefA(float4 r[8], const float* __restrict__ Ab,
                                      int n0, int N, int tid) {
    #pragma unroll
    for (int t = 0; t < 8; t++) {
        int idx = tid + t * 512;
        int row = idx >> 5, c4 = (idx & 31) * 4;
        int n = n0 + row;
        float4 v = make_float4(0.f, 0.f, 0.f, 0.f);
        if (n < N) v = *(const float4*)(Ab + (size_t)n * D + c4);
        r[t] = v;
    }
}
__device__ __forceinline__ void stageB(char* smem, int buf, int seg, int tid) {
    uint32_t dh = smem_u32(smem + V_B0 + buf * V_BSZ);
    const uint4* srcH = (const uint4*)(g_Wh + (size_t)seg * D * D);
    const uint4* srcL = (const uint4*)(g_Wl + (size_t)seg * D * D);
    #pragma unroll
    for (int i = 0; i < 4; i++) {
        int f = tid + i * 512;
        int k = f >> 4, c8 = (f & 15) * 8;
        uint32_t off = (uint32_t)((k * AST + c8) * 2);
        CP_ASYNC16(dh + off, srcH + f, 16);
        CP_ASYNC16(dh + V_HALF + off, srcL + f, 16);
    }
    CP_COMMIT();
}

__global__ void __launch_bounds__(512, 1)
k_final(const float* __restrict__ x,
        const float* __restrict__ b_types, const float* __restrict__ b_self,
        const float* __restrict__ b_e2,
        const float* __restrict__ ln_g, const float* __restrict__ ln_b,
        float* __restrict__ out, int N) {
    extern __shared__ char smem[];
    __shared__ float Ps[1024];
    uint32_t sb = smem_u32(smem);
    __nv_bfloat16* Ah = (__nv_bfloat16*)smem;
    __nv_bfloat16* Al = (__nv_bfloat16*)(smem + V_HALF);
    int tid = threadIdx.x, wid = tid >> 5, lane = tid & 31;
    int n0 = blockIdx.x * 128;
    int rg = wid & 3, cg = wid >> 2;           // 4 x 4 warp grid

    for (int f = tid; f < 1024; f += 512) {
        float v;
        if (f < 512)      v = b_types[f];
        else if (f < 640) v = b_e2[f - 512];
        else if (f < 768) v = b_self[f - 640];
        else if (f < 896) v = ln_g[f - 768];
        else              v = ln_b[f - 896];
        Ps[f] = v;
    }

    stageB((char*)smem, 0, 0, tid);
    float4 r[8];
    prefA(r, seg_src(0, x, N), n0, N, tid);

    float acc[2][4][4] = {};
    #pragma unroll
    for (int seg = 0; seg < 6; seg++) {
        __syncthreads();
        #pragma unroll
        for (int t = 0; t < 8; t++) {
            int idx = tid + t * 512;
            int row = idx >> 5, c4 = (idx & 31) * 4;
            store4_split(Ah + row * AST, Al + row * AST, c4, r[t]);
        }
        if (seg < 5) {
            stageB((char*)smem, (seg + 1) & 1, seg + 1, tid);
            prefA(r, seg_src(seg + 1, x, N), n0, N, tid);
            CP_WAIT1();
        } else {
            CP_WAIT0();
        }
        __syncthreads();

        uint32_t bBase = sb + (uint32_t)(V_B0 + (seg & 1) * V_BSZ);
        #pragma unroll
        for (int ks = 0; ks < 8; ks++) {
            uint32_t ah0, ah1, ah2, ah3, al0, al1, al2, al3;
            uint32_t bfr[4][2][2];
            #pragma unroll
            for (int nt = 0; nt < 4; nt++) {
                uint32_t ba = bBase + (uint32_t)(((ks * 16 + (lane & 15)) * AST
                                                  + cg * 32 + nt * 8) * 2);
                LDMX2T(bfr[nt][0][0], bfr[nt][0][1], ba);
                LDMX2T(bfr[nt][1][0], bfr[nt][1][1], ba + V_HALF);
            }
            #pragma unroll
            for (int rt = 0; rt < 2; rt++) {
                uint32_t ao = sb + (uint32_t)(((rg * 32 + rt * 16 + (lane & 15)) * AST
                                               + (lane >> 4) * 8 + ks * 16) * 2);
                LDMX4(ah0, ah1, ah2, ah3, ao);
                LDMX4(al0, al1, al2, al3, ao + V_HALF);
                #pragma unroll
                for (int nt = 0; nt < 4; nt++) {
                    MMA_BF16(acc[rt][nt], al0, al1, al2, al3,
                             bfr[nt][0][0], bfr[nt][0][1]);
                    MMA_BF16(acc[rt][nt], ah0, ah1, ah2, ah3,
                             bfr[nt][1][0], bfr[nt][1][1]);
                    MMA_BF16(acc[rt][nt], ah0, ah1, ah2, ah3,
                             bfr[nt][0][0], bfr[nt][0][1]);
                }
            }
        }
    }

    // Epilogue: acc -> S (overlay A region), then LN + ReLU + store.
    __syncthreads();
    float* S = (float*)smem;   // [128][132]
    {
        int cp = (lane & 3) * 2;
        #pragma unroll
        for (int rt = 0; rt < 2; rt++) {
            int r0 = rg * 32 + rt * 16 + (lane >> 2);
            #pragma unroll
            for (int nt = 0; nt < 4; nt++) {
                int c = cg * 32 + nt * 8 + cp;
                S[r0 * 132 + c]           = acc[rt][nt][0];
                S[r0 * 132 + c + 1]       = acc[rt][nt][1];
                S[(r0 + 8) * 132 + c]     = acc[rt][nt][2];
                S[(r0 + 8) * 132 + c + 1] = acc[rt][nt][3];
            }
        }
    }
    __syncthreads();

    for (int it = 0; it < 8; it++) {
        int rr = wid * 8 + it;
        int n = n0 + rr;
        bool valid = n < N;
        float c0 = 0.f, c1 = 0.f, c2 = 0.f, c3 = 0.f;
        if (valid) {
            c0 = (float)__ldg(&g_cnt[0 * N + n]);
            c1 = (float)__ldg(&g_cnt[1 * N + n]);
            c2 = (float)__ldg(&g_cnt[2 * N + n]);
            c3 = (float)__ldg(&g_cnt[3 * N + n]);
        }
        float ct = c0 + c1 + c2 + c3;
        float v[4];
        float s1 = 0.f, s2 = 0.f;
        #pragma unroll
        for (int j = 0; j < 4; j++) {
            int col = lane * 4 + j;
            float val = S[rr * 132 + col]
                + c0 * Ps[0 * D + col] + c1 * Ps[1 * D + col]
                + c2 * Ps[2 * D + col] + c3 * Ps[3 * D + col]
                + ct * Ps[512 + col] + Ps[640 + col];
            v[j] = val;
            s1 += val;
            s2 += val * val;
        }
        #pragma unroll
        for (int m = 1; m < 32; m <<= 1) {
            s1 += __shfl_xor_sync(0xffffffff, s1, m);
            s2 += __shfl_xor_sync(0xffffffff, s2, m);
        }
        float mean = s1 * (1.f / D);
        float var  = s2 * (1.f / D) - mean * mean;
        float inv  = rsqrtf(var + 1e-5f);
        if (valid) {
            float4 o;
            #pragma unroll
            for (int j = 0; j < 4; j++) {
                int col = lane * 4 + j;
                float rres = (v[j] - mean) * inv * Ps[768 + col] + Ps[896 + col];
                (&o.x)[j] = rres > 0.f ? rres : 0.f;
            }
            *(float4*)(out + (size_t)n * D + lane * 4) = o;
        }
    }
}

// ---------------------------------------------------------------------------
extern "C" void kernel_launch(void* const* d_in, const int* in_sizes, int n_in,
                              void* d_out, int out_size) {
    const float* x   = (const float*)d_in[0];
    const int*   ei  = (const int*)d_in[1];
    const int*   et  = (const int*)d_in[2];
    const float* ef  = (const float*)d_in[3];
    const float* Wt  = (const float*)d_in[4];
    const float* bt  = (const float*)d_in[5];
    const float* Ws  = (const float*)d_in[6];
    const float* bs  = (const float*)d_in[7];
    const float* W1  = (const float*)d_in[8];
    const float* b1  = (const float*)d_in[9];
    const float* W2  = (const float*)d_in[10];
    const float* b2  = (const float*)d_in[11];
    const float* lg  = (const float*)d_in[12];
    const float* lb  = (const float*)d_in[13];
    float* out = (float*)d_out;

    int N = in_sizes[0] / D;
    int E = in_sizes[2];
    int ntiles = (E + 127) / 128;
    int mlp_grid = ntiles < 148 ? ntiles : 148;

    cudaFuncSetAttribute(k_edge_mlp, cudaFuncAttributeMaxDynamicSharedMemorySize, P_SMEM);
    cudaFuncSetAttribute(k_final,    cudaFuncAttributeMaxDynamicSharedMemorySize, V_SMEM);

    k_split_w<<<(7 * D * D / 2 + 255) / 256, 256>>>(Wt, W2, Ws, W1);
    k_zero<<<2048, 256>>>(N);
    k_scatter<<<(E + 7) / 8, 256>>>(x, ei, et, N, E);
    k_edge_mlp<<<mlp_grid, 256, P_SMEM>>>(ef, ei, b1, E, ntiles);
    k_final<<<(N + 127) / 128, 512, V_SMEM>>>(x, bt, bs, b2, lg, lb, out, N);
}